// round 13
// baseline (speedup 1.0000x reference)
#include <cuda_runtime.h>

#define BB 2
#define LL 8192
#define HH 16
#define DD 64
#define CC 64
#define NCH 128                    // LL/CC
#define NW  (BB*NCH*HH)            // 4096 chunk-head work items
#define YSIZE ((size_t)BB*LL*HH*2*DD)   // 33,554,432
#define PF 8                       // prefetch depth
#define SEG 16                     // replay segment length
#define NSEG (CC/SEG)              // 4 segments per chunk

// Scratch
__device__ float g_cp[(size_t)NW * 4 * 128];  // checkpoints t=15,31,47,63: local_h
__device__ float g_Pcp[(size_t)NW * 4 * 4];   // checkpoints: inclusive cum gate P
__device__ float g_d[(size_t)NW * CC * 2];    // raw per-step delta d_t

__device__ __forceinline__ float4 f4fma(float s, float4 x, float4 acc) {
    return make_float4(fmaf(s, x.x, acc.x), fmaf(s, x.y, acc.y),
                       fmaf(s, x.z, acc.z), fmaf(s, x.w, acc.w));
}
__device__ __forceinline__ float4 f4scale(float s, float4 x) {
    return make_float4(s * x.x, s * x.y, s * x.z, s * x.w);
}
__device__ __forceinline__ float f4dot(float4 a, float4 b) {
    return a.x*b.x + a.y*b.y + a.z*b.z + a.w*b.w;
}

// ---------------------------------------------------------------------------
// No-op pad kernel: shifts ncu's "-s 5 -c 1" capture window so the profiled
// launch (index 5) is k_replay instead of k_local1.
// ---------------------------------------------------------------------------
__global__ void k_prof_pad() {}

// ---------------------------------------------------------------------------
// Pass 1: intra-chunk scan (CHUNK=64, reference semantics). FOUR chunk-heads
// per warp (8 lanes each, 8 d-values per lane). Emits per-step delta d_t and
// checkpoints (local_h, P) every 16 steps; checkpoint 3 doubles as
// final_h/total_A for the inter-chunk scan.
// ---------------------------------------------------------------------------
__global__ __launch_bounds__(128) void k_local1(
    const float* __restrict__ Ag, const float* __restrict__ Kg,
    const float* __restrict__ Vg, const float* __restrict__ Bg)
{
    int warp = (blockIdx.x * blockDim.x + threadIdx.x) >> 5;
    int lane = threadIdx.x & 31;
    int g    = lane & 7;
    int hd   = 4 * warp + (lane >> 3);

    int h = hd % HH;
    int c = (hd / HH) % NCH;
    int b = hd / (HH * NCH);
    size_t base = ((size_t)b * LL + (size_t)c * CC) * HH + h;
    size_t db   = (size_t)hd * CC;

    float4 aB[PF]; float2 vB[PF]; float bB[PF]; float4 kB[PF][2];
#pragma unroll
    for (int i = 0; i < PF; i++) {
        size_t idx = base + (size_t)i * HH;
        aB[i]    = __ldg((const float4*)(Ag + idx * 4));
        vB[i]    = __ldg((const float2*)(Vg + idx * 2));
        bB[i]    = __ldg(Bg + idx);
        kB[i][0] = __ldg((const float4*)(Kg + idx * 64 + 8 * g));
        kB[i][1] = __ldg((const float4*)(Kg + idx * 64 + 8 * g + 4));
    }

    float4 h0[2], h1[2];
#pragma unroll
    for (int j = 0; j < 2; j++) {
        h0[j] = make_float4(0.f, 0.f, 0.f, 0.f);
        h1[j] = make_float4(0.f, 0.f, 0.f, 0.f);
    }
    float p00 = 1.f, p01 = 0.f, p10 = 0.f, p11 = 1.f;

    for (int t = 0; t < CC; t += PF) {
#pragma unroll
        for (int u = 0; u < PF; u++) {
            float4 a  = aB[u];
            float2 v  = vB[u];
            float  bt = bB[u];
            float4 k0 = kB[u][0], k1 = kB[u][1];

            int tn = t + u + PF;
            if (tn < CC) {
                size_t idx = base + (size_t)tn * HH;
                aB[u]    = __ldg((const float4*)(Ag + idx * 4));
                vB[u]    = __ldg((const float2*)(Vg + idx * 2));
                bB[u]    = __ldg(Bg + idx);
                kB[u][0] = __ldg((const float4*)(Kg + idx * 64 + 8 * g));
                kB[u][1] = __ldg((const float4*)(Kg + idx * 64 + 8 * g + 4));
            }

            // propagate: hp = A * h
            float4 hp0[2], hp1[2];
#pragma unroll
            for (int j = 0; j < 2; j++) {
                hp0[j] = f4fma(a.y, h1[j], f4scale(a.x, h0[j]));
                hp1[j] = f4fma(a.w, h1[j], f4scale(a.z, h0[j]));
            }

            // read = k . hp : 8-wide local dot, 3-level group reduce
            float r0 = f4dot(hp0[0], k0) + f4dot(hp0[1], k1);
            float r1 = f4dot(hp1[0], k0) + f4dot(hp1[1], k1);
#pragma unroll
            for (int o = 4; o; o >>= 1) {
                r0 += __shfl_xor_sync(0xffffffffu, r0, o);
                r1 += __shfl_xor_sync(0xffffffffu, r1, o);
            }

            float d0 = bt * (v.x - r0);
            float d1 = bt * (v.y - r1);
            h0[0] = f4fma(d0, k0, hp0[0]);  h0[1] = f4fma(d0, k1, hp0[1]);
            h1[0] = f4fma(d1, k0, hp1[0]);  h1[1] = f4fma(d1, k1, hp1[1]);

            // cumulative 2x2 gate product (inclusive)
            float q00 = a.x * p00 + a.y * p10;
            float q01 = a.x * p01 + a.y * p11;
            float q10 = a.z * p00 + a.w * p10;
            float q11 = a.z * p01 + a.w * p11;
            p00 = q00; p01 = q01; p10 = q10; p11 = q11;

            if (g == 0)
                ((float2*)g_d)[db + (size_t)(t + u)] = make_float2(d0, d1);

            // checkpoint every SEG steps (t+u = 15, 31, 47, 63)
            if (((t + u) & (SEG - 1)) == SEG - 1) {
                int j = (t + u) >> 4;
                float4* cp = (float4*)(g_cp + ((size_t)hd * 4 + j) * 128);
                cp[2 * g + 0]      = h0[0];
                cp[2 * g + 1]      = h0[1];
                cp[16 + 2 * g + 0] = h1[0];
                cp[16 + 2 * g + 1] = h1[1];
                if (g == 0)
                    ((float4*)g_Pcp)[(size_t)hd * 4 + j] =
                        make_float4(p00, p01, p10, p11);
            }
        }
    }
}

// ---------------------------------------------------------------------------
// Pass 2: inter-chunk scan per (b,h); consumes checkpoint 3 (final_h/total_A);
// writes chunk_states (pre-update carry) straight into the output tail.
// ---------------------------------------------------------------------------
__global__ __launch_bounds__(64) void k_inter(float* __restrict__ cs)
{
    int b = blockIdx.x / HH;
    int h = blockIdx.x % HH;
    int d = threadIdx.x;

    float s0 = 0.f, s1 = 0.f;
#pragma unroll 8
    for (int c = 0; c < NCH; c++) {
        size_t w = ((size_t)b * NCH + c) * HH + h;
        cs[(w * 2 + 0) * 64 + d] = s0;
        cs[(w * 2 + 1) * 64 + d] = s1;
        const float* at = g_Pcp + (w * 4 + 3) * 4;
        float a00 = __ldg(at + 0), a01 = __ldg(at + 1);
        float a10 = __ldg(at + 2), a11 = __ldg(at + 3);
        const float* hf = g_cp + (w * 4 + 3) * 128;
        float hf0 = __ldg(hf + d);
        float hf1 = __ldg(hf + 64 + d);
        float n0 = a00 * s0 + a01 * s1 + hf0;
        float n1 = a10 * s0 + a11 * s1 + hf1;
        s0 = n0; s1 = n1;
    }
}

// ---------------------------------------------------------------------------
// Pass 3: checkpointed shuffle-free replay. One 16-lane group per
// (chunk-head, segment); 16384 units, 8192 warps.
//   v_init = cp_h[seg-1] + P_cp[seg-1] * s   (seg 0: v_init = s)
//   v_t = A_t v_{t-1} + d_t k_t^T ;  Y_t = v_t      (exact playback)
// Y stores use __stwt (no L2 allocate) so K/A stay L2-resident from pass 1;
// single-use streams use __ldcs (evict-first).
// ---------------------------------------------------------------------------
__global__ __launch_bounds__(128) void k_replay(
    const float* __restrict__ Ag, const float* __restrict__ Kg,
    const float* __restrict__ cs, float* __restrict__ Y)
{
    int warp = (blockIdx.x * blockDim.x + threadIdx.x) >> 5;
    int lane = threadIdx.x & 31;
    int g    = lane & 15;
    int uid  = 2 * warp + (lane >> 4);   // 0..16383, hd fastest
    int hd   = uid & (NW - 1);
    int seg  = uid >> 12;                // uid / NW

    int h = hd % HH;
    int c = (hd / HH) % NCH;
    int b = hd / (HH * NCH);
    int t0 = seg * SEG;
    size_t base = ((size_t)b * LL + (size_t)c * CC + t0) * HH + h;
    size_t db   = (size_t)hd * CC + t0;

    const float4* sp = (const float4*)(cs + (size_t)hd * 128);
    float4 s0 = __ldcs(sp + g);
    float4 s1 = __ldcs(sp + 16 + g);

    float4 v0, v1;
    if (seg == 0) {
        v0 = s0; v1 = s1;
    } else {
        const float4* cp = (const float4*)(g_cp + ((size_t)hd * 4 + seg - 1) * 128);
        float4 c0 = __ldcs(cp + g);
        float4 c1 = __ldcs(cp + 16 + g);
        float4 P  = __ldcs(((const float4*)g_Pcp) + (size_t)hd * 4 + seg - 1);
        v0 = f4fma(P.y, s1, f4fma(P.x, s0, c0));
        v1 = f4fma(P.w, s1, f4fma(P.z, s0, c1));
    }

    float4 kB[PF]; float2 dB[PF]; float4 aB[PF];
#pragma unroll
    for (int i = 0; i < PF; i++) {
        size_t idx = base + (size_t)i * HH;
        kB[i] = __ldg((const float4*)(Kg + idx * 64 + 4 * g));
        dB[i] = __ldcs(((const float2*)g_d) + db + i);
        aB[i] = __ldg((const float4*)(Ag + idx * 4));
    }

    for (int t = 0; t < SEG; t += PF) {
#pragma unroll
        for (int u = 0; u < PF; u++) {
            float4 kk = kB[u];
            float2 dd = dB[u];
            float4 a  = aB[u];

            int tn = t + u + PF;
            if (tn < SEG) {
                size_t idx = base + (size_t)tn * HH;
                kB[u] = __ldg((const float4*)(Kg + idx * 64 + 4 * g));
                dB[u] = __ldcs(((const float2*)g_d) + db + tn);
                aB[u] = __ldg((const float4*)(Ag + idx * 4));
            }

            float4 n0 = f4fma(dd.x, kk, f4fma(a.y, v1, f4scale(a.x, v0)));
            float4 n1 = f4fma(dd.y, kk, f4fma(a.w, v1, f4scale(a.z, v0)));
            v0 = n0; v1 = n1;

            size_t idx = base + (size_t)(t + u) * HH;
            float4* yo = (float4*)(Y + idx * 128);
            __stwt(yo + g,      v0);
            __stwt(yo + 16 + g, v1);
        }
    }
}

extern "C" void kernel_launch(void* const* d_in, const int* in_sizes, int n_in,
                              void* d_out, int out_size)
{
    const float* A    = (const float*)d_in[0];
    const float* K    = (const float*)d_in[1];
    const float* V    = (const float*)d_in[2];
    const float* beta = (const float*)d_in[3];
    float* Y  = (float*)d_out;
    float* cs = Y + YSIZE;   // chunk_states tail of the output buffer

    // Pad launches: put k_replay at global launch index 5 for the ncu window.
    k_prof_pad<<<1, 32>>>();
    k_prof_pad<<<1, 32>>>();
    k_prof_pad<<<1, 32>>>();

    k_local1<<<NW / 16, 128>>>(A, K, V, beta);       // 1024 warps, 4 heads each
    k_inter<<<BB * HH, 64>>>(cs);
    k_replay<<<(NW * NSEG) / 8, 128>>>(A, K, cs, Y); // 8192 warps, 2 units each
}

// round 14
// speedup vs baseline: 1.2601x; 1.2601x over previous
#include <cuda_runtime.h>

#define BB 2
#define LL 8192
#define HH 16
#define DD 64
#define CC 64
#define NCH 128                    // LL/CC
#define NW  (BB*NCH*HH)            // 4096 chunk-head work items
#define YSIZE ((size_t)BB*LL*HH*2*DD)   // 33,554,432
#define PF 8                       // prefetch depth
#define SEG 16                     // replay segment length
#define NSEG (CC/SEG)              // 4 segments per chunk

#define ISUB 8                     // inter-scan subgroups per (b,h)
#define ICH  (NCH/ISUB)            // 16 chunks per subgroup
#define ISMEM ((ISUB*(ICH+1)*128 + ISUB*(ICH+1)*4 + ISUB*128) * 4)

// Scratch
__device__ float g_cp[(size_t)NW * 4 * 128];  // checkpoints t=15,31,47,63: local_h
__device__ float g_Pcp[(size_t)NW * 4 * 4];   // checkpoints: inclusive cum gate P
__device__ float g_d[(size_t)NW * CC * 2];    // raw per-step delta d_t

__device__ __forceinline__ float4 f4fma(float s, float4 x, float4 acc) {
    return make_float4(fmaf(s, x.x, acc.x), fmaf(s, x.y, acc.y),
                       fmaf(s, x.z, acc.z), fmaf(s, x.w, acc.w));
}
__device__ __forceinline__ float4 f4scale(float s, float4 x) {
    return make_float4(s * x.x, s * x.y, s * x.z, s * x.w);
}
__device__ __forceinline__ float f4dot(float4 a, float4 b) {
    return a.x*b.x + a.y*b.y + a.z*b.z + a.w*b.w;
}

// ---------------------------------------------------------------------------
// Pass 1: intra-chunk scan (CHUNK=64, reference semantics). FOUR chunk-heads
// per warp (8 lanes each, 8 d-values per lane). Emits per-step delta d_t and
// checkpoints (local_h, P) every 16 steps; checkpoint 3 doubles as
// final_h/total_A for the inter-chunk scan.
// ---------------------------------------------------------------------------
__global__ __launch_bounds__(128) void k_local1(
    const float* __restrict__ Ag, const float* __restrict__ Kg,
    const float* __restrict__ Vg, const float* __restrict__ Bg)
{
    int warp = (blockIdx.x * blockDim.x + threadIdx.x) >> 5;
    int lane = threadIdx.x & 31;
    int g    = lane & 7;
    int hd   = 4 * warp + (lane >> 3);

    int h = hd % HH;
    int c = (hd / HH) % NCH;
    int b = hd / (HH * NCH);
    size_t base = ((size_t)b * LL + (size_t)c * CC) * HH + h;
    size_t db   = (size_t)hd * CC;

    float4 aB[PF]; float2 vB[PF]; float bB[PF]; float4 kB[PF][2];
#pragma unroll
    for (int i = 0; i < PF; i++) {
        size_t idx = base + (size_t)i * HH;
        aB[i]    = __ldg((const float4*)(Ag + idx * 4));
        vB[i]    = __ldg((const float2*)(Vg + idx * 2));
        bB[i]    = __ldg(Bg + idx);
        kB[i][0] = __ldg((const float4*)(Kg + idx * 64 + 8 * g));
        kB[i][1] = __ldg((const float4*)(Kg + idx * 64 + 8 * g + 4));
    }

    float4 h0[2], h1[2];
#pragma unroll
    for (int j = 0; j < 2; j++) {
        h0[j] = make_float4(0.f, 0.f, 0.f, 0.f);
        h1[j] = make_float4(0.f, 0.f, 0.f, 0.f);
    }
    float p00 = 1.f, p01 = 0.f, p10 = 0.f, p11 = 1.f;

    for (int t = 0; t < CC; t += PF) {
#pragma unroll
        for (int u = 0; u < PF; u++) {
            float4 a  = aB[u];
            float2 v  = vB[u];
            float  bt = bB[u];
            float4 k0 = kB[u][0], k1 = kB[u][1];

            int tn = t + u + PF;
            if (tn < CC) {
                size_t idx = base + (size_t)tn * HH;
                aB[u]    = __ldg((const float4*)(Ag + idx * 4));
                vB[u]    = __ldg((const float2*)(Vg + idx * 2));
                bB[u]    = __ldg(Bg + idx);
                kB[u][0] = __ldg((const float4*)(Kg + idx * 64 + 8 * g));
                kB[u][1] = __ldg((const float4*)(Kg + idx * 64 + 8 * g + 4));
            }

            // propagate: hp = A * h
            float4 hp0[2], hp1[2];
#pragma unroll
            for (int j = 0; j < 2; j++) {
                hp0[j] = f4fma(a.y, h1[j], f4scale(a.x, h0[j]));
                hp1[j] = f4fma(a.w, h1[j], f4scale(a.z, h0[j]));
            }

            // read = k . hp : 8-wide local dot, 3-level group reduce
            float r0 = f4dot(hp0[0], k0) + f4dot(hp0[1], k1);
            float r1 = f4dot(hp1[0], k0) + f4dot(hp1[1], k1);
#pragma unroll
            for (int o = 4; o; o >>= 1) {
                r0 += __shfl_xor_sync(0xffffffffu, r0, o);
                r1 += __shfl_xor_sync(0xffffffffu, r1, o);
            }

            float d0 = bt * (v.x - r0);
            float d1 = bt * (v.y - r1);
            h0[0] = f4fma(d0, k0, hp0[0]);  h0[1] = f4fma(d0, k1, hp0[1]);
            h1[0] = f4fma(d1, k0, hp1[0]);  h1[1] = f4fma(d1, k1, hp1[1]);

            // cumulative 2x2 gate product (inclusive)
            float q00 = a.x * p00 + a.y * p10;
            float q01 = a.x * p01 + a.y * p11;
            float q10 = a.z * p00 + a.w * p10;
            float q11 = a.z * p01 + a.w * p11;
            p00 = q00; p01 = q01; p10 = q10; p11 = q11;

            if (g == 0)
                ((float2*)g_d)[db + (size_t)(t + u)] = make_float2(d0, d1);

            // checkpoint every SEG steps (t+u = 15, 31, 47, 63)
            if (((t + u) & (SEG - 1)) == SEG - 1) {
                int j = (t + u) >> 4;
                float4* cp = (float4*)(g_cp + ((size_t)hd * 4 + j) * 128);
                cp[2 * g + 0]      = h0[0];
                cp[2 * g + 1]      = h0[1];
                cp[16 + 2 * g + 0] = h1[0];
                cp[16 + 2 * g + 1] = h1[1];
                if (g == 0)
                    ((float4*)g_Pcp)[(size_t)hd * 4 + j] =
                        make_float4(p00, p01, p10, p11);
            }
        }
    }
}

// ---------------------------------------------------------------------------
// Pass 2: inter-chunk scan per (b,h) as an EXACT two-level parallel scan
// (reassociation only, no inverses). One 512-thread block per (b,h):
//   A) 8 subgroups x 64 d-lanes scan 16 chunks each from zero state,
//      storing per-chunk carries z and exclusive 2x2 prefixes Q in smem.
//   B) 64 threads scan the 8 subgroup totals (8 serial steps).
//   C) all threads emit carry = Q*S + z for all 128 chunks to cs.
// Serial depth 128 -> 16+8; 512 warps chip-wide instead of 64.
// ---------------------------------------------------------------------------
__global__ __launch_bounds__(512) void k_inter(float* __restrict__ cs)
{
    extern __shared__ float sm[];
    float* zS = sm;                                   // [8][17][128]
    float* qS = zS + ISUB * (ICH + 1) * 128;          // [8][17][4]
    float* sS = qS + ISUB * (ICH + 1) * 4;            // [8][128]

    int b   = blockIdx.x / HH;
    int h   = blockIdx.x % HH;
    int tid = threadIdx.x;
    int sub = tid >> 6;          // 0..7
    int d   = tid & 63;

    size_t wbase = ((size_t)b * NCH + sub * ICH) * HH + h;

    // Pass A: subgroup-local affine scan from zero state
    float s0 = 0.f, s1 = 0.f;
    float q00 = 1.f, q01 = 0.f, q10 = 0.f, q11 = 1.f;
#pragma unroll 4
    for (int i = 0; i < ICH; i++) {
        size_t w = wbase + (size_t)i * HH;
        const float* at = g_Pcp + (w * 4 + 3) * 4;
        float a00 = __ldg(at + 0), a01 = __ldg(at + 1);
        float a10 = __ldg(at + 2), a11 = __ldg(at + 3);
        float hf0 = __ldg(g_cp + (w * 4 + 3) * 128 + d);
        float hf1 = __ldg(g_cp + (w * 4 + 3) * 128 + 64 + d);

        float* zp = zS + (sub * (ICH + 1) + i) * 128;
        zp[d] = s0; zp[64 + d] = s1;
        if (d == 0) {
            float* qp = qS + (sub * (ICH + 1) + i) * 4;
            qp[0] = q00; qp[1] = q01; qp[2] = q10; qp[3] = q11;
        }

        float n0 = fmaf(a00, s0, fmaf(a01, s1, hf0));
        float n1 = fmaf(a10, s0, fmaf(a11, s1, hf1));
        s0 = n0; s1 = n1;
        float t00 = a00 * q00 + a01 * q10, t01 = a00 * q01 + a01 * q11;
        float t10 = a10 * q00 + a11 * q10, t11 = a10 * q01 + a11 * q11;
        q00 = t00; q01 = t01; q10 = t10; q11 = t11;
    }
    {
        float* zp = zS + (sub * (ICH + 1) + ICH) * 128;
        zp[d] = s0; zp[64 + d] = s1;
        if (d == 0) {
            float* qp = qS + (sub * (ICH + 1) + ICH) * 4;
            qp[0] = q00; qp[1] = q01; qp[2] = q10; qp[3] = q11;
        }
    }
    __syncthreads();

    // Pass B: scan subgroup totals (8 serial steps, 64 threads)
    if (tid < 64) {
        float c0 = 0.f, c1 = 0.f;
#pragma unroll
        for (int s = 0; s < ISUB; s++) {
            sS[s * 128 + d]      = c0;
            sS[s * 128 + 64 + d] = c1;
            const float* qp = qS + (s * (ICH + 1) + ICH) * 4;
            const float* zp = zS + (s * (ICH + 1) + ICH) * 128;
            float n0 = fmaf(qp[0], c0, fmaf(qp[1], c1, zp[d]));
            float n1 = fmaf(qp[2], c0, fmaf(qp[3], c1, zp[64 + d]));
            c0 = n0; c1 = n1;
        }
    }
    __syncthreads();

    // Pass C: emit all 128 carries
    float S0 = sS[sub * 128 + d];
    float S1 = sS[sub * 128 + 64 + d];
#pragma unroll 4
    for (int i = 0; i < ICH; i++) {
        const float* qp = qS + (sub * (ICH + 1) + i) * 4;
        const float* zp = zS + (sub * (ICH + 1) + i) * 128;
        float c0 = fmaf(qp[0], S0, fmaf(qp[1], S1, zp[d]));
        float c1 = fmaf(qp[2], S0, fmaf(qp[3], S1, zp[64 + d]));
        size_t w = wbase + (size_t)i * HH;
        cs[(w * 2 + 0) * 64 + d] = c0;
        cs[(w * 2 + 1) * 64 + d] = c1;
    }
}

// ---------------------------------------------------------------------------
// Pass 3: checkpointed shuffle-free replay. One 16-lane group per
// (chunk-head, segment); 16384 units, 8192 warps.
//   v_init = cp_h[seg-1] + P_cp[seg-1] * s   (seg 0: v_init = s)
//   v_t = A_t v_{t-1} + d_t k_t^T ;  Y_t = v_t      (exact playback)
// ---------------------------------------------------------------------------
__global__ __launch_bounds__(128) void k_replay(
    const float* __restrict__ Ag, const float* __restrict__ Kg,
    const float* __restrict__ cs, float* __restrict__ Y)
{
    int warp = (blockIdx.x * blockDim.x + threadIdx.x) >> 5;
    int lane = threadIdx.x & 31;
    int g    = lane & 15;
    int uid  = 2 * warp + (lane >> 4);   // 0..16383, hd fastest
    int hd   = uid & (NW - 1);
    int seg  = uid >> 12;                // uid / NW

    int h = hd % HH;
    int c = (hd / HH) % NCH;
    int b = hd / (HH * NCH);
    int t0 = seg * SEG;
    size_t base = ((size_t)b * LL + (size_t)c * CC + t0) * HH + h;
    size_t db   = (size_t)hd * CC + t0;

    const float4* sp = (const float4*)(cs + (size_t)hd * 128);
    float4 s0 = __ldg(sp + g);
    float4 s1 = __ldg(sp + 16 + g);

    float4 v0, v1;
    if (seg == 0) {
        v0 = s0; v1 = s1;
    } else {
        const float4* cp = (const float4*)(g_cp + ((size_t)hd * 4 + seg - 1) * 128);
        float4 c0 = __ldg(cp + g);
        float4 c1 = __ldg(cp + 16 + g);
        float4 P  = __ldg(((const float4*)g_Pcp) + (size_t)hd * 4 + seg - 1);
        v0 = f4fma(P.y, s1, f4fma(P.x, s0, c0));
        v1 = f4fma(P.w, s1, f4fma(P.z, s0, c1));
    }

    float4 kB[PF]; float2 dB[PF]; float4 aB[PF];
#pragma unroll
    for (int i = 0; i < PF; i++) {
        size_t idx = base + (size_t)i * HH;
        kB[i] = __ldg((const float4*)(Kg + idx * 64 + 4 * g));
        dB[i] = __ldg(((const float2*)g_d) + db + i);
        aB[i] = __ldg((const float4*)(Ag + idx * 4));
    }

    for (int t = 0; t < SEG; t += PF) {
#pragma unroll
        for (int u = 0; u < PF; u++) {
            float4 kk = kB[u];
            float2 dd = dB[u];
            float4 a  = aB[u];

            int tn = t + u + PF;
            if (tn < SEG) {
                size_t idx = base + (size_t)tn * HH;
                kB[u] = __ldg((const float4*)(Kg + idx * 64 + 4 * g));
                dB[u] = __ldg(((const float2*)g_d) + db + tn);
                aB[u] = __ldg((const float4*)(Ag + idx * 4));
            }

            float4 n0 = f4fma(dd.x, kk, f4fma(a.y, v1, f4scale(a.x, v0)));
            float4 n1 = f4fma(dd.y, kk, f4fma(a.w, v1, f4scale(a.z, v0)));
            v0 = n0; v1 = n1;

            size_t idx = base + (size_t)(t + u) * HH;
            float4* yo = (float4*)(Y + idx * 128);
            __stcs(yo + g,      v0);
            __stcs(yo + 16 + g, v1);
        }
    }
}

extern "C" void kernel_launch(void* const* d_in, const int* in_sizes, int n_in,
                              void* d_out, int out_size)
{
    const float* A    = (const float*)d_in[0];
    const float* K    = (const float*)d_in[1];
    const float* V    = (const float*)d_in[2];
    const float* beta = (const float*)d_in[3];
    float* Y  = (float*)d_out;
    float* cs = Y + YSIZE;   // chunk_states tail of the output buffer

    cudaFuncSetAttribute(k_inter, cudaFuncAttributeMaxDynamicSharedMemorySize,
                         ISMEM);

    k_local1<<<NW / 16, 128>>>(A, K, V, beta);       // 1024 warps, 4 heads each
    k_inter<<<BB * HH, 512, ISMEM>>>(cs);            // parallel two-level scan
    k_replay<<<(NW * NSEG) / 8, 128>>>(A, K, cs, Y); // 8192 warps, 2 units each
}